// round 1
// baseline (speedup 1.0000x reference)
#include <cuda_runtime.h>
#include <math.h>

#define BATCH  2
#define SEQ    2048
#define HIDDEN 1024
#define INNER  2048
#define STATE  64
#define KCONV  4
#define M_TOT  (BATCH * SEQ)          // 4096
#define XZW    (2 * INNER)            // 4096

// ---------------- scratch (device globals: no runtime alloc allowed) -------
__device__ float g_xz [M_TOT * XZW];    // [M, 4096]  (x_inner | z)
__device__ float g_xc [M_TOT * INNER];  // conv+silu output
__device__ float g_a  [M_TOT * INNER];  // dt_pre, then a = exp(-dt) in-place
__device__ float g_dtx[M_TOT * INNER];  // dt * xc
__device__ float g_Bm [M_TOT * STATE];
__device__ float g_Cm [M_TOT * STATE];
__device__ float g_y  [M_TOT * INNER];  // gated scan output

// ---------------- generic tiled SGEMM: C = A[MxK] * B[KxN] (+bias[n]) ------
// 128x128 tile, K-step 8, 256 threads, 8x8 accumulators per thread.
__global__ void __launch_bounds__(256)
sgemm_kernel(const float* __restrict__ A, const float* __restrict__ B,
             float* __restrict__ C, const float* __restrict__ bias,
             int M, int N, int K)
{
    __shared__ float As[8][128];
    __shared__ float Bs[8][128];

    const int tid = threadIdx.x;
    const int bm  = blockIdx.y * 128;
    const int bn  = blockIdx.x * 128;

    // A tile loader: thread -> (row, 4 consecutive k)
    const int a_m = tid >> 1;
    const int a_k = (tid & 1) * 4;
    // B tile loader: thread -> (k, 4 consecutive n)
    const int b_k = tid >> 5;
    const int b_n = (tid & 31) * 4;

    const int rm = (tid >> 4) * 8;
    const int rn = (tid & 15) * 8;

    float acc[8][8];
#pragma unroll
    for (int i = 0; i < 8; i++)
#pragma unroll
        for (int j = 0; j < 8; j++) acc[i][j] = 0.f;

    for (int k0 = 0; k0 < K; k0 += 8) {
        // load A tile (M here is always a multiple of 128)
        float4 av = *(const float4*)&A[(size_t)(bm + a_m) * K + k0 + a_k];
        As[a_k + 0][a_m] = av.x;
        As[a_k + 1][a_m] = av.y;
        As[a_k + 2][a_m] = av.z;
        As[a_k + 3][a_m] = av.w;

        // load B tile (guard for N=64 case)
        float4 bv = make_float4(0.f, 0.f, 0.f, 0.f);
        if (bn + b_n < N)
            bv = *(const float4*)&B[(size_t)(k0 + b_k) * N + bn + b_n];
        *(float4*)&Bs[b_k][b_n] = bv;

        __syncthreads();

#pragma unroll
        for (int kk = 0; kk < 8; kk++) {
            float a_reg[8], b_reg[8];
            *(float4*)&a_reg[0] = *(const float4*)&As[kk][rm];
            *(float4*)&a_reg[4] = *(const float4*)&As[kk][rm + 4];
            *(float4*)&b_reg[0] = *(const float4*)&Bs[kk][rn];
            *(float4*)&b_reg[4] = *(const float4*)&Bs[kk][rn + 4];
#pragma unroll
            for (int i = 0; i < 8; i++)
#pragma unroll
                for (int j = 0; j < 8; j++)
                    acc[i][j] = fmaf(a_reg[i], b_reg[j], acc[i][j]);
        }
        __syncthreads();
    }

#pragma unroll
    for (int i = 0; i < 8; i++) {
        const int row = bm + rm + i;
#pragma unroll
        for (int j = 0; j < 8; j++) {
            const int col = bn + rn + j;
            if (col < N) {
                float v = acc[i][j];
                if (bias) v += bias[col];
                C[(size_t)row * N + col] = v;
            }
        }
    }
}

// ---------------- causal depthwise conv1d + silu ---------------------------
__global__ void conv_silu_kernel(const float* __restrict__ conv_w,
                                 const float* __restrict__ conv_b)
{
    int idx = blockIdx.x * blockDim.x + threadIdx.x;
    if (idx >= M_TOT * INNER) return;
    const int i = idx % INNER;
    const int m = idx / INNER;
    const int l = m % SEQ;

    float acc = conv_b[i];
    const size_t base = (size_t)m * XZW + i;
#pragma unroll
    for (int k = 0; k < KCONV; k++) {
        int ll = l + k - (KCONV - 1);
        if (ll >= 0)
            acc = fmaf(conv_w[i * KCONV + k],
                       g_xz[base + (size_t)(k - (KCONV - 1)) * XZW], acc);
    }
    // silu
    g_xc[idx] = acc / (1.f + expf(-acc));
}

// ---------------- dt epilogue: softplus -> a = exp(-dt), dtx = dt*xc -------
__global__ void dt_epilogue_kernel()
{
    int idx = blockIdx.x * blockDim.x + threadIdx.x;
    if (idx >= M_TOT * INNER) return;
    float v = g_a[idx];                 // dt_pre + b_dt (bias fused in GEMM)
    float dt = (v > 20.f) ? v : log1pf(expf(v));
    g_a[idx]   = expf(-dt);
    g_dtx[idx] = dt * g_xc[idx];
}

// ---------------- sequential selective scan: warp per (b, i) channel -------
// state update: s = a_t * s + dtx_t * B_t[n];  y_t = sum_n s[n] * C_t[n]
// 64 states -> 2 per lane; fused skip (D*xc) and output gate (silu(z)).
__global__ void __launch_bounds__(128)
scan_kernel(const float* __restrict__ Dv)
{
    const int warp = (blockIdx.x * blockDim.x + threadIdx.x) >> 5;
    const int lane = threadIdx.x & 31;
    const int b = warp / INNER;
    const int i = warp % INNER;

    float s0 = 0.f, s1 = 0.f;
    const float Di = Dv[i];

    for (int t = 0; t < SEQ; t++) {
        const int row = b * SEQ + t;
        const float a  = g_a  [(size_t)row * INNER + i];
        const float dx = g_dtx[(size_t)row * INNER + i];
        const float B0 = g_Bm[(size_t)row * STATE + lane];
        const float B1 = g_Bm[(size_t)row * STATE + lane + 32];
        const float C0 = g_Cm[(size_t)row * STATE + lane];
        const float C1 = g_Cm[(size_t)row * STATE + lane + 32];

        s0 = fmaf(a, s0, dx * B0);
        s1 = fmaf(a, s1, dx * B1);

        float p = fmaf(s0, C0, s1 * C1);
#pragma unroll
        for (int off = 16; off > 0; off >>= 1)
            p += __shfl_down_sync(0xffffffffu, p, off);

        if (lane == 0) {
            const float xc = g_xc[(size_t)row * INNER + i];
            const float z  = g_xz[(size_t)row * XZW + INNER + i];
            const float zg = z / (1.f + expf(-z));   // silu(z)
            g_y[(size_t)row * INNER + i] = (p + Di * xc) * zg;
        }
    }
}

// ---------------------------------------------------------------------------
extern "C" void kernel_launch(void* const* d_in, const int* in_sizes, int n_in,
                              void* d_out, int out_size)
{
    const float* x      = (const float*)d_in[0];
    const float* W_in   = (const float*)d_in[1];
    const float* conv_w = (const float*)d_in[2];
    const float* conv_b = (const float*)d_in[3];
    const float* W_dt   = (const float*)d_in[4];
    const float* b_dt   = (const float*)d_in[5];
    const float* W_B    = (const float*)d_in[6];
    const float* W_C    = (const float*)d_in[7];
    const float* Dv     = (const float*)d_in[8];
    const float* W_out  = (const float*)d_in[9];
    float* out = (float*)d_out;

    float *xz, *xc, *a, *dtx, *Bm, *Cm, *y;
    cudaGetSymbolAddress((void**)&xz,  g_xz);
    cudaGetSymbolAddress((void**)&xc,  g_xc);
    cudaGetSymbolAddress((void**)&a,   g_a);
    cudaGetSymbolAddress((void**)&dtx, g_dtx);
    cudaGetSymbolAddress((void**)&Bm,  g_Bm);
    cudaGetSymbolAddress((void**)&Cm,  g_Cm);
    cudaGetSymbolAddress((void**)&y,   g_y);

    const int ew_threads = 256;
    const int ew_blocks  = (M_TOT * INNER + ew_threads - 1) / ew_threads;

    // 1. xz = x @ W_in                         [4096,1024]x[1024,4096]
    sgemm_kernel<<<dim3(XZW / 128, M_TOT / 128), 256>>>(
        x, W_in, xz, nullptr, M_TOT, XZW, HIDDEN);

    // 2. causal depthwise conv + silu -> xc
    conv_silu_kernel<<<ew_blocks, ew_threads>>>(conv_w, conv_b);

    // 3. dt_pre = xc @ W_dt + b_dt             [4096,2048]x[2048,2048]
    sgemm_kernel<<<dim3(INNER / 128, M_TOT / 128), 256>>>(
        xc, W_dt, a, b_dt, M_TOT, INNER, INNER);

    // 4. a = exp(-softplus(dt_pre)), dtx = dt * xc
    dt_epilogue_kernel<<<ew_blocks, ew_threads>>>();

    // 5. B, C projections                      [4096,2048]x[2048,64]
    sgemm_kernel<<<dim3(1, M_TOT / 128), 256>>>(
        xc, W_B, Bm, nullptr, M_TOT, STATE, INNER);
    sgemm_kernel<<<dim3(1, M_TOT / 128), 256>>>(
        xc, W_C, Cm, nullptr, M_TOT, STATE, INNER);

    // 6. selective scan + skip + output gate -> y
    scan_kernel<<<(BATCH * INNER) / 4, 128>>>(Dv);

    // 7. out = y @ W_out                       [4096,2048]x[2048,1024]
    sgemm_kernel<<<dim3(HIDDEN / 128, M_TOT / 128), 256>>>(
        y, W_out, out, nullptr, M_TOT, HIDDEN, INNER);
}

// round 2
// speedup vs baseline: 1.7624x; 1.7624x over previous
#include <cuda_runtime.h>
#include <math.h>
#include <stdint.h>

#define BATCH  2
#define SEQ    2048
#define HIDDEN 1024
#define INNER  2048
#define STATE  64
#define KCONV  4
#define M_TOT  (BATCH * SEQ)          // 4096
#define XZW    (2 * INNER)            // 4096

// GEMM tiling
#define BM 128
#define BN 128
#define BK 32
#define APITCH 36                      // floats; 16B-aligned rows, ldmatrix conflict-free
#define BPITCH 136                     // floats; (8k+n)%32 distinct -> conflict-free b-frag LDS
#define A_TILE_FLOATS (BM * APITCH)    // 4608
#define B_TILE_FLOATS (BK * BPITCH)    // 4352
#define STAGE_FLOATS  (A_TILE_FLOATS + B_TILE_FLOATS)   // 8960
#define SMEM_BYTES    (2 * STAGE_FLOATS * 4)            // 71680

// ---------------- scratch (device globals: no runtime alloc allowed) -------
__device__ float g_xz [M_TOT * XZW];    // [M, 4096]  (x_inner | z)
__device__ float g_xc [M_TOT * INNER];  // conv+silu output
__device__ float g_a  [M_TOT * INNER];  // a = exp(-dt)
__device__ float g_dtx[M_TOT * INNER];  // dt * xc
__device__ float g_Bm [M_TOT * STATE];
__device__ float g_Cm [M_TOT * STATE];
__device__ float g_y  [M_TOT * INNER];  // gated scan output

// ---------------- small PTX helpers ----------------------------------------
__device__ __forceinline__ uint32_t cvt_tf32(float x) {
    uint32_t r;
    asm("cvt.rna.tf32.f32 %0, %1;" : "=r"(r) : "f"(x));
    return r;
}
__device__ __forceinline__ uint32_t smem_u32(const void* p) {
    return (uint32_t)__cvta_generic_to_shared(p);
}
__device__ __forceinline__ void cp_async16(uint32_t dst, const void* src, bool pred) {
    int sz = pred ? 16 : 0;
    asm volatile("cp.async.cg.shared.global [%0], [%1], 16, %2;\n"
                 :: "r"(dst), "l"(src), "r"(sz));
}
__device__ __forceinline__ void cp_commit() {
    asm volatile("cp.async.commit_group;\n");
}
template <int N>
__device__ __forceinline__ void cp_wait() {
    asm volatile("cp.async.wait_group %0;\n" :: "n"(N));
}
__device__ __forceinline__ void ldmatrix_x4(uint32_t& r0, uint32_t& r1,
                                            uint32_t& r2, uint32_t& r3,
                                            uint32_t addr) {
    asm volatile("ldmatrix.sync.aligned.m8n8.x4.shared.b16 {%0,%1,%2,%3}, [%4];"
                 : "=r"(r0), "=r"(r1), "=r"(r2), "=r"(r3) : "r"(addr));
}
__device__ __forceinline__ void mma_tf32(float* c, const uint32_t* a, const uint32_t* b) {
    asm volatile(
        "mma.sync.aligned.m16n8k8.row.col.f32.tf32.tf32.f32 "
        "{%0,%1,%2,%3}, {%4,%5,%6,%7}, {%8,%9}, {%0,%1,%2,%3};"
        : "+f"(c[0]), "+f"(c[1]), "+f"(c[2]), "+f"(c[3])
        : "r"(a[0]), "r"(a[1]), "r"(a[2]), "r"(a[3]), "r"(b[0]), "r"(b[1]));
}
__device__ __forceinline__ float softplus_f(float v) {
    return (v > 20.f) ? v : log1pf(expf(v));
}

// ---------------- TF32 tensor-core GEMM -------------------------------------
// C[M,N] = A[M,K] @ B[K,N]   (row-major).
// mode 0: C = acc (+ bias[col] if bias != nullptr)
// mode 1: dt epilogue: dt = softplus(acc + bias[col]);
//         C[m,n] = exp(-dt); C2[m,n] = dt * xc_src[m,n]
__global__ void __launch_bounds__(256, 2)
gemm_tf32(const float* __restrict__ A, const float* __restrict__ B,
          float* __restrict__ C, const float* __restrict__ bias,
          const float* __restrict__ xc_src, float* __restrict__ C2,
          int M, int N, int K, int mode)
{
    extern __shared__ float sm[];
    const int tid  = threadIdx.x;
    const int lane = tid & 31;
    const int warp = tid >> 5;
    const int bm   = blockIdx.y * BM;
    const int bn   = blockIdx.x * BN;
    const int wm   = (warp >> 2) * 64;   // 2 warps in M
    const int wn   = (warp & 3) * 32;    // 4 warps in N

    const uint32_t smb = smem_u32(sm);

    // per-thread cp.async destinations / sources
    // A tile: 128 rows x 32 k = 1024 float4; 4 per thread
    const int a_row = tid >> 1;              // unused pattern replaced below
    (void)a_row;

    // ldmatrix per-thread base (mi = kk = 0)
    const int lgrp = lane >> 3;              // 0..3
    const int lrow = (lane & 7) + ((lgrp & 1) << 3);
    const int lkof = (lgrp >> 1) * 4;
    // b-frag per-thread base offsets (floats)
    const int b_k = lane & 3;
    const int b_n = wn + (lane >> 2);

    float acc[4][4][4];
#pragma unroll
    for (int i = 0; i < 4; i++)
#pragma unroll
        for (int j = 0; j < 4; j++)
#pragma unroll
            for (int r = 0; r < 4; r++) acc[i][j][r] = 0.f;

    const int T = K / BK;

    // ---- tile loader ----
    auto load_tile = [&](int s, int k0) {
        const uint32_t a_dst0 = smb + (uint32_t)(s * STAGE_FLOATS) * 4u;
        const uint32_t b_dst0 = a_dst0 + A_TILE_FLOATS * 4u;
#pragma unroll
        for (int p = 0; p < 4; p++) {
            int idx = tid + p * 256;         // 0..1023
            int row = idx >> 3;
            int c4  = (idx & 7) * 4;
            cp_async16(a_dst0 + (uint32_t)(row * APITCH + c4) * 4u,
                       A + (size_t)(bm + row) * K + k0 + c4, true);
        }
#pragma unroll
        for (int p = 0; p < 4; p++) {
            int idx = tid + p * 256;
            int k   = idx >> 5;
            int n4  = (idx & 31) * 4;
            bool pred = (bn + n4) < N;
            int nsrc = pred ? (bn + n4) : 0;
            cp_async16(b_dst0 + (uint32_t)(k * BPITCH + n4) * 4u,
                       B + (size_t)(k0 + k) * N + nsrc, pred);
        }
    };

    load_tile(0, 0);
    cp_commit();

    for (int t = 0; t < T; t++) {
        if (t + 1 < T) {
            load_tile((t + 1) & 1, (t + 1) * BK);
            cp_commit();
            cp_wait<1>();
        } else {
            cp_wait<0>();
        }
        __syncthreads();

        const int s = t & 1;
        const uint32_t As_u = smb + (uint32_t)(s * STAGE_FLOATS) * 4u;
        const float*   Bs_f = sm + s * STAGE_FLOATS + A_TILE_FLOATS;
        const uint32_t a_base = As_u + (uint32_t)((wm + lrow) * APITCH + lkof) * 4u;
        const float*   b_base = Bs_f + b_k * BPITCH + b_n;

#pragma unroll
        for (int kk = 0; kk < 4; kk++) {
            uint32_t afrag[4][4];
#pragma unroll
            for (int mi = 0; mi < 4; mi++) {
                uint32_t r0, r1, r2, r3;
                ldmatrix_x4(r0, r1, r2, r3,
                            a_base + (uint32_t)(mi * 16 * APITCH + kk * 8) * 4u);
                afrag[mi][0] = cvt_tf32(__uint_as_float(r0));
                afrag[mi][1] = cvt_tf32(__uint_as_float(r1));
                afrag[mi][2] = cvt_tf32(__uint_as_float(r2));
                afrag[mi][3] = cvt_tf32(__uint_as_float(r3));
            }
            uint32_t bfrag[4][2];
#pragma unroll
            for (int nj = 0; nj < 4; nj++) {
                bfrag[nj][0] = cvt_tf32(b_base[kk * 8 * BPITCH + nj * 8]);
                bfrag[nj][1] = cvt_tf32(b_base[(kk * 8 + 4) * BPITCH + nj * 8]);
            }
#pragma unroll
            for (int mi = 0; mi < 4; mi++)
#pragma unroll
                for (int nj = 0; nj < 4; nj++)
                    mma_tf32(acc[mi][nj], afrag[mi], bfrag[nj]);
        }
        __syncthreads();
    }

    // ---- epilogue ----
    const int er = bm + wm + (lane >> 2);
    const int ec = bn + wn + (lane & 3) * 2;
#pragma unroll
    for (int mi = 0; mi < 4; mi++) {
#pragma unroll
        for (int nj = 0; nj < 4; nj++) {
            const int col = ec + nj * 8;
            if (col >= N) continue;
            const float bv0 = bias ? bias[col]     : 0.f;
            const float bv1 = bias ? bias[col + 1] : 0.f;
#pragma unroll
            for (int h = 0; h < 2; h++) {          // h=0 -> rows r, h=1 -> r+8
                const int row = er + mi * 16 + h * 8;
                float v0 = acc[mi][nj][2 * h + 0] + bv0;
                float v1 = acc[mi][nj][2 * h + 1] + bv1;
                const size_t off = (size_t)row * N + col;
                if (mode == 0) {
                    float2 o; o.x = v0; o.y = v1;
                    *(float2*)&C[off] = o;
                } else {
                    float dt0 = softplus_f(v0);
                    float dt1 = softplus_f(v1);
                    float2 av; av.x = expf(-dt0); av.y = expf(-dt1);
                    *(float2*)&C[off] = av;
                    float2 xc = *(const float2*)&xc_src[off];
                    float2 dx; dx.x = dt0 * xc.x; dx.y = dt1 * xc.y;
                    *(float2*)&C2[off] = dx;
                }
            }
        }
    }
}

// ---------------- causal depthwise conv1d + silu ---------------------------
__global__ void conv_silu_kernel(const float* __restrict__ conv_w,
                                 const float* __restrict__ conv_b)
{
    int idx = blockIdx.x * blockDim.x + threadIdx.x;
    if (idx >= M_TOT * INNER) return;
    const int i = idx % INNER;
    const int m = idx / INNER;
    const int l = m % SEQ;

    float acc = conv_b[i];
    const size_t base = (size_t)m * XZW + i;
#pragma unroll
    for (int k = 0; k < KCONV; k++) {
        int ll = l + k - (KCONV - 1);
        if (ll >= 0)
            acc = fmaf(conv_w[i * KCONV + k],
                       g_xz[base + (size_t)(k - (KCONV - 1)) * XZW], acc);
    }
    g_xc[idx] = acc / (1.f + expf(-acc));   // silu
}

// ---------------- sequential selective scan: warp per (b, i) channel -------
__global__ void __launch_bounds__(128)
scan_kernel(const float* __restrict__ Dv)
{
    const int warp = (blockIdx.x * blockDim.x + threadIdx.x) >> 5;
    const int lane = threadIdx.x & 31;
    const int b = warp / INNER;
    const int i = warp % INNER;

    float s0 = 0.f, s1 = 0.f;
    const float Di = Dv[i];

    for (int t = 0; t < SEQ; t++) {
        const int row = b * SEQ + t;
        const float a  = g_a  [(size_t)row * INNER + i];
        const float dx = g_dtx[(size_t)row * INNER + i];
        const float B0 = g_Bm[(size_t)row * STATE + lane];
        const float B1 = g_Bm[(size_t)row * STATE + lane + 32];
        const float C0 = g_Cm[(size_t)row * STATE + lane];
        const float C1 = g_Cm[(size_t)row * STATE + lane + 32];

        s0 = fmaf(a, s0, dx * B0);
        s1 = fmaf(a, s1, dx * B1);

        float p = fmaf(s0, C0, s1 * C1);
#pragma unroll
        for (int off = 16; off > 0; off >>= 1)
            p += __shfl_down_sync(0xffffffffu, p, off);

        if (lane == 0) {
            const float xc = g_xc[(size_t)row * INNER + i];
            const float z  = g_xz[(size_t)row * XZW + INNER + i];
            const float zg = z / (1.f + expf(-z));   // silu(z)
            g_y[(size_t)row * INNER + i] = (p + Di * xc) * zg;
        }
    }
}

// ---------------------------------------------------------------------------
extern "C" void kernel_launch(void* const* d_in, const int* in_sizes, int n_in,
                              void* d_out, int out_size)
{
    const float* x      = (const float*)d_in[0];
    const float* W_in   = (const float*)d_in[1];
    const float* conv_w = (const float*)d_in[2];
    const float* conv_b = (const float*)d_in[3];
    const float* W_dt   = (const float*)d_in[4];
    const float* b_dt   = (const float*)d_in[5];
    const float* W_B    = (const float*)d_in[6];
    const float* W_C    = (const float*)d_in[7];
    const float* Dv     = (const float*)d_in[8];
    const float* W_out  = (const float*)d_in[9];
    float* out = (float*)d_out;

    float *xz, *xc, *a, *dtx, *Bm, *Cm, *y;
    cudaGetSymbolAddress((void**)&xz,  g_xz);
    cudaGetSymbolAddress((void**)&xc,  g_xc);
    cudaGetSymbolAddress((void**)&a,   g_a);
    cudaGetSymbolAddress((void**)&dtx, g_dtx);
    cudaGetSymbolAddress((void**)&Bm,  g_Bm);
    cudaGetSymbolAddress((void**)&Cm,  g_Cm);
    cudaGetSymbolAddress((void**)&y,   g_y);

    static bool attr_set = false;
    if (!attr_set) {
        cudaFuncSetAttribute(gemm_tf32,
                             cudaFuncAttributeMaxDynamicSharedMemorySize,
                             SMEM_BYTES);
        attr_set = true;
    }

    const int ew_threads = 256;
    const int ew_blocks  = (M_TOT * INNER + ew_threads - 1) / ew_threads;

    // 1. xz = x @ W_in                [4096,1024] x [1024,4096]
    gemm_tf32<<<dim3(XZW / BN, M_TOT / BM), 256, SMEM_BYTES>>>(
        x, W_in, xz, nullptr, nullptr, nullptr, M_TOT, XZW, HIDDEN, 0);

    // 2. causal depthwise conv + silu -> xc
    conv_silu_kernel<<<ew_blocks, ew_threads>>>(conv_w, conv_b);

    // 3. dt GEMM + fused epilogue: a = exp(-softplus(.)), dtx = dt*xc
    gemm_tf32<<<dim3(INNER / BN, M_TOT / BM), 256, SMEM_BYTES>>>(
        xc, W_dt, a, b_dt, xc, dtx, M_TOT, INNER, INNER, 1);

    // 4. B, C projections             [4096,2048] x [2048,64]
    gemm_tf32<<<dim3(1, M_TOT / BM), 256, SMEM_BYTES>>>(
        xc, W_B, Bm, nullptr, nullptr, nullptr, M_TOT, STATE, INNER, 0);
    gemm_tf32<<<dim3(1, M_TOT / BM), 256, SMEM_BYTES>>>(
        xc, W_C, Cm, nullptr, nullptr, nullptr, M_TOT, STATE, INNER, 0);

    // 5. selective scan + skip + output gate -> y
    scan_kernel<<<(BATCH * INNER) / 4, 128>>>(Dv);

    // 6. out = y @ W_out              [4096,2048] x [2048,1024]
    gemm_tf32<<<dim3(HIDDEN / BN, M_TOT / BM), 256, SMEM_BYTES>>>(
        y, W_out, out, nullptr, nullptr, nullptr, M_TOT, HIDDEN, INNER, 0);
}